// round 3
// baseline (speedup 1.0000x reference)
#include <cuda_runtime.h>
#include <math.h>

#define N_B 16
#define D 128
#define L0 2048
#define L1 1024
#define H 384
#define CHUNK 64
#define CH0 (L0/CHUNK)  // 32
#define CH1 (L1/CHUNK)  // 16

#define TR 64
#define XROW 129
#define WROW 129

// Scratch (device globals; no allocation allowed)
__device__ float g_pm1[2][N_B][CH0][D];
__device__ float g_pm2[2][N_B][CH0][D];
__device__ int   g_pam[2][N_B][CH0][D];
__device__ float g_top1[2][N_B][D];
__device__ float g_delta[2][N_B][D];
__device__ int   g_amax[2][N_B][D];
__device__ float g_base[2][N_B][D];

// ---------------------------------------------------------------------------
// Stage 1: per-chunk top2 + argmax over L, one thread per d (coalesced reads)
// ---------------------------------------------------------------------------
__global__ void reduce_partial(const float* __restrict__ x, int g, int L) {
    int n = blockIdx.y, c = blockIdx.x, d = threadIdx.x;
    const float* p = x + ((size_t)n * L + (size_t)c * CHUNK) * D + d;
    float m1 = -INFINITY, m2 = -INFINITY;
    int am = 0;
    #pragma unroll 4
    for (int r = 0; r < CHUNK; ++r) {
        float v = p[(size_t)r * D];
        if (v > m1) { m2 = m1; m1 = v; am = c * CHUNK + r; }
        else if (v > m2) { m2 = v; }
    }
    g_pm1[g][n][c][d] = m1;
    g_pm2[g][n][c][d] = m2;
    g_pam[g][n][c][d] = am;
}

// ---------------------------------------------------------------------------
// Stage 2: merge chunk partials -> global top1 / (top2-top1) / argmax
// (ascending chunk order + strict compare == jnp first-occurrence argmax;
//  ties give delta = 0 so argmax choice is irrelevant anyway)
// ---------------------------------------------------------------------------
__global__ void reduce_final() {
    int n = blockIdx.x, g = blockIdx.y, d = threadIdx.x;
    int CH = g ? CH1 : CH0;
    float m1 = -INFINITY, m2 = -INFINITY;
    int am = 0;
    for (int c = 0; c < CH; ++c) {
        float p1 = g_pm1[g][n][c][d];
        float p2 = g_pm2[g][n][c][d];
        int   pa = g_pam[g][n][c][d];
        if (p1 > m1) { m2 = fmaxf(m1, p2); m1 = p1; am = pa; }
        else         { m2 = fmaxf(m2, p1); }
    }
    g_top1[g][n][d]  = m1;
    g_delta[g][n][d] = m2 - m1;   // <= 0; 0 on duplicates
    g_amax[g][n][d]  = am;
}

// ---------------------------------------------------------------------------
// Stage 3: per-(group,n,o) bias:
//   base = b[o] + sum_d top1_x0[n,d]*W[o,128+d] + sum_d top1_x1[n,d]*W[o,256+d]
// (slot1 is always an x0-derived max, slot2 always x1-derived, both groups)
// ---------------------------------------------------------------------------
__global__ void base_kernel(const float* __restrict__ W0, const float* __restrict__ b0,
                            const float* __restrict__ W1, const float* __restrict__ b1) {
    int n = blockIdx.x, g = blockIdx.y, o = threadIdx.x;
    const float* W = g ? W1 : W0;
    const float* b = g ? b1 : b0;
    __shared__ float t0[D], t1[D];
    t0[o] = g_top1[0][n][o];
    t1[o] = g_top1[1][n][o];
    __syncthreads();
    float s = b[o];
    const float* w1r = W + (size_t)o * H + D;
    const float* w2r = W + (size_t)o * H + 2 * D;
    #pragma unroll 8
    for (int d = 0; d < D; ++d) s += t0[d] * w1r[d];
    #pragma unroll 8
    for (int d = 0; d < D; ++d) s += t1[d] * w2r[d];
    g_base[g][n][o] = s;
}

// ---------------------------------------------------------------------------
// Stage 4: y[n,l,o] = sum_k x[n,l,k] * W[o,k]  + base[g][n][o]
//          + (for d with argmax[n,d]==l) delta[n,d] * W[o, wboff+d]
// Block: 64 rows x 128 cols. Thread: 4 rows (strided by 16) x 8 cols.
// All hot-loop smem accesses conflict-free (pad=1 + strided row assignment).
// ---------------------------------------------------------------------------
__global__ void __launch_bounds__(256, 2)
gemm_kernel(const float* __restrict__ x, const float* __restrict__ W,
            float* __restrict__ y, int g, int L, int wboff) {
    extern __shared__ float sm[];
    float* Xs = sm;                 // [TR][XROW]
    float* Ws = sm + TR * XROW;     // [D][WROW]

    int n    = blockIdx.y;
    int row0 = blockIdx.x * TR;
    int tid  = threadIdx.x;

    // Stage x tile (scalar, coalesced LDG + conflict-free STS)
    const float* xb = x + ((size_t)n * L + row0) * D;
    #pragma unroll
    for (int i = tid; i < TR * D; i += 256) {
        int r = i >> 7, k = i & 127;
        Xs[r * XROW + k] = xb[(size_t)r * D + k];
    }
    // Stage Wa = first 128 columns of W (row-major [o][k])
    #pragma unroll
    for (int i = tid; i < D * D; i += 256) {
        int o = i >> 7, k = i & 127;
        Ws[o * WROW + k] = W[(size_t)o * H + k];
    }
    __syncthreads();

    int rowg = tid & 15;   // thread rows: rowg + 16*i, i=0..3
    int colg = tid >> 4;   // thread cols: colg*8 + j, j=0..7
    int c0 = colg * 8;

    float acc[4][8];
    #pragma unroll
    for (int i = 0; i < 4; ++i)
        #pragma unroll
        for (int j = 0; j < 8; ++j) acc[i][j] = 0.0f;

    #pragma unroll 4
    for (int k = 0; k < D; ++k) {
        float xf[4], wf[8];
        #pragma unroll
        for (int i = 0; i < 4; ++i) xf[i] = Xs[(rowg + 16 * i) * XROW + k];
        #pragma unroll
        for (int j = 0; j < 8; ++j) wf[j] = Ws[(c0 + j) * WROW + k];
        #pragma unroll
        for (int i = 0; i < 4; ++i)
            #pragma unroll
            for (int j = 0; j < 8; ++j)
                acc[i][j] += xf[i] * wf[j];
    }

    // Add per-(n,o) bias
    #pragma unroll
    for (int j = 0; j < 8; ++j) {
        float bz = g_base[g][n][c0 + j];
        #pragma unroll
        for (int i = 0; i < 4; ++i) acc[i][j] += bz;
    }

    // Sparse LOO corrections (deterministic: fixed ascending-d order)
    for (int d = 0; d < D; ++d) {
        int am = g_amax[g][n][d];
        int lr = am - row0;
        if ((unsigned)lr < (unsigned)TR) {
            int off = lr - rowg;
            if ((off & 15) == 0) {
                int i = off >> 4;
                if ((unsigned)i < 4u) {
                    float dv = g_delta[g][n][d];
                    #pragma unroll
                    for (int j = 0; j < 8; ++j)
                        acc[i][j] += dv * W[(size_t)(c0 + j) * H + wboff + d];
                }
            }
        }
    }

    // Store
    float* yb = y + ((size_t)n * L + row0) * D;
    #pragma unroll
    for (int i = 0; i < 4; ++i) {
        float* yr = yb + (size_t)(rowg + 16 * i) * D + c0;
        float4 v0 = make_float4(acc[i][0], acc[i][1], acc[i][2], acc[i][3]);
        float4 v1 = make_float4(acc[i][4], acc[i][5], acc[i][6], acc[i][7]);
        *reinterpret_cast<float4*>(yr)     = v0;
        *reinterpret_cast<float4*>(yr + 4) = v1;
    }
}

// ---------------------------------------------------------------------------
extern "C" void kernel_launch(void* const* d_in, const int* in_sizes, int n_in,
                              void* d_out, int out_size) {
    (void)in_sizes; (void)n_in; (void)out_size;
    const float* x0 = (const float*)d_in[0];
    const float* x1 = (const float*)d_in[1];
    const float* W0 = (const float*)d_in[2];
    const float* b0 = (const float*)d_in[3];
    const float* W1 = (const float*)d_in[4];
    const float* b1 = (const float*)d_in[5];
    float* y0 = (float*)d_out;
    float* y1 = (float*)d_out + (size_t)N_B * L0 * D;

    const size_t smem = (size_t)(TR * XROW + D * WROW) * sizeof(float); // 99072 B
    cudaFuncSetAttribute(gemm_kernel,
                         cudaFuncAttributeMaxDynamicSharedMemorySize, (int)smem);

    reduce_partial<<<dim3(CH0, N_B), 128>>>(x0, 0, L0);
    reduce_partial<<<dim3(CH1, N_B), 128>>>(x1, 1, L1);
    reduce_final<<<dim3(N_B, 2), 128>>>();
    base_kernel<<<dim3(N_B, 2), 128>>>(W0, b0, W1, b1);
    gemm_kernel<<<dim3(L0 / TR, N_B), 256, smem>>>(x0, W0, y0, 0, L0, 128);
    gemm_kernel<<<dim3(L1 / TR, N_B), 256, smem>>>(x1, W1, y1, 1, L1, 256);
}

// round 4
// speedup vs baseline: 1.0733x; 1.0733x over previous
#include <cuda_runtime.h>
#include <math.h>

#define N_B 16
#define D 128
#define L0 2048
#define L1 1024
#define H 384
#define CHUNK 64
#define CH0 (L0/CHUNK)  // 32
#define CH1 (L1/CHUNK)  // 16

// GEMM tiling: 128 rows x 128 cols per block, 8x8 per thread (strided maps)
#define BM 128
#define XROW 129          // smem row stride (conflict-free)
#define OROW 132          // output restage stride (float4-aligned + low conflict)
#define TILES0 (L0/BM)    // 16
#define TILES1 (L1/BM)    // 8
#define NBLK0 (N_B*TILES0)  // 256
#define NBLK1 (N_B*TILES1)  // 128

// Scratch (device globals; no allocation allowed)
__device__ float g_pm1[2][N_B][CH0][D];
__device__ float g_pm2[2][N_B][CH0][D];
__device__ int   g_pam[2][N_B][CH0][D];
__device__ float g_top1[2][N_B][D];
__device__ float g_delta[2][N_B][D];
__device__ int   g_amax[2][N_B][D];
__device__ float g_base[2][N_B][D];

// ---- f32x2 packed helpers (Blackwell FFMA2 via PTX) ----------------------
__device__ __forceinline__ unsigned long long pk2(float lo, float hi) {
    unsigned long long r;
    asm("mov.b64 %0, {%1,%2};" : "=l"(r) : "f"(lo), "f"(hi));
    return r;
}
__device__ __forceinline__ void upk2(unsigned long long v, float& lo, float& hi) {
    asm("mov.b64 {%0,%1}, %2;" : "=f"(lo), "=f"(hi) : "l"(v));
}
__device__ __forceinline__ unsigned long long fma2(unsigned long long a,
                                                   unsigned long long b,
                                                   unsigned long long c) {
    unsigned long long d;
    asm("fma.rn.f32x2 %0, %1, %2, %3;" : "=l"(d) : "l"(a), "l"(b), "l"(c));
    return d;
}

// ---------------------------------------------------------------------------
// Stage 1: per-chunk top2 + argmax over L (both groups in one launch).
// One thread per d (coalesced); explicit 8-wide load batches for MLP.
// ---------------------------------------------------------------------------
__global__ void reduce_partial(const float* __restrict__ x0,
                               const float* __restrict__ x1) {
    int n = blockIdx.y, c = blockIdx.x, d = threadIdx.x;
    int g, cc, L;
    const float* x;
    if (c < CH0) { g = 0; cc = c;       L = L0; x = x0; }
    else         { g = 1; cc = c - CH0; L = L1; x = x1; }
    const float* p = x + ((size_t)n * L + (size_t)cc * CHUNK) * D + d;
    float m1 = -INFINITY, m2 = -INFINITY;
    int am = 0;
    for (int r0 = 0; r0 < CHUNK; r0 += 8) {
        float v[8];
        #pragma unroll
        for (int u = 0; u < 8; ++u) v[u] = p[(size_t)(r0 + u) * D];
        #pragma unroll
        for (int u = 0; u < 8; ++u) {
            if (v[u] > m1) { m2 = m1; m1 = v[u]; am = cc * CHUNK + r0 + u; }
            else if (v[u] > m2) { m2 = v[u]; }
        }
    }
    g_pm1[g][n][cc][d] = m1;
    g_pm2[g][n][cc][d] = m2;
    g_pam[g][n][cc][d] = am;
}

// ---------------------------------------------------------------------------
// Stage 2: merge chunk partials -> global top1 / (top2-top1) / argmax
// (ascending chunk order + strict compare == first-occurrence argmax;
//  ties give delta = 0 so argmax choice is irrelevant anyway)
// ---------------------------------------------------------------------------
__global__ void reduce_final() {
    int n = blockIdx.x, g = blockIdx.y, d = threadIdx.x;
    int CH = g ? CH1 : CH0;
    float m1 = -INFINITY, m2 = -INFINITY;
    int am = 0;
    for (int c = 0; c < CH; ++c) {
        float p1 = g_pm1[g][n][c][d];
        float p2 = g_pm2[g][n][c][d];
        int   pa = g_pam[g][n][c][d];
        if (p1 > m1) { m2 = fmaxf(m1, p2); m1 = p1; am = pa; }
        else         { m2 = fmaxf(m2, p1); }
    }
    g_top1[g][n][d]  = m1;
    g_delta[g][n][d] = m2 - m1;   // <= 0; 0 on duplicates
    g_amax[g][n][d]  = am;
}

// ---------------------------------------------------------------------------
// Stage 3: per-(group,n,o) bias. Coalesced: lanes over contiguous dd axis,
// warp-shfl reduce, 16 warps x 8 o's each.
//   base = b[o] + sum_dd tv[dd] * W[o, 128+dd],  tv = [top1_x0 | top1_x1]
// ---------------------------------------------------------------------------
__global__ void base_kernel(const float* __restrict__ W0, const float* __restrict__ b0,
                            const float* __restrict__ W1, const float* __restrict__ b1) {
    int n = blockIdx.x, g = blockIdx.y;
    const float* W = g ? W1 : W0;
    const float* b = g ? b1 : b0;
    int tid = threadIdx.x;           // 512
    __shared__ float tv[2 * D];
    if (tid < D)            tv[tid] = g_top1[0][n][tid];
    else if (tid < 2 * D)   tv[tid] = g_top1[1][n][tid - D];
    __syncthreads();
    int lane = tid & 31, w = tid >> 5;   // 16 warps
    #pragma unroll
    for (int oo = 0; oo < 8; ++oo) {
        int o = w + 16 * oo;
        const float* wr = W + (size_t)o * H + D;
        float s = 0.0f;
        #pragma unroll
        for (int c = 0; c < 8; ++c) {
            int dd = lane + 32 * c;
            s += tv[dd] * wr[dd];
        }
        #pragma unroll
        for (int off = 16; off; off >>= 1)
            s += __shfl_down_sync(0xffffffffu, s, off);
        if (lane == 0) g_base[g][n][o] = s + b[o];
    }
}

// ---------------------------------------------------------------------------
// Stage 4: y[n,l,o] = sum_k x[n,l,k]*W[o,k] + base[g][n][o]
//          + (for d with argmax[n,d]==l) delta[n,d]*W[o, wboff+d]
// Single launch covering both groups (384 blocks). 128x128 tile, 8x8/thread
// (rows rowg+16i, cols colg+16j -> all hot LDS conflict-free), f32x2 FFMA2
// inner product, output restaged through smem for coalesced float4 STG.
// ---------------------------------------------------------------------------
__global__ void __launch_bounds__(256, 1)
gemm_kernel(const float* __restrict__ x0, const float* __restrict__ x1,
            const float* __restrict__ W0, const float* __restrict__ W1,
            float* __restrict__ yout) {
    extern __shared__ float sm[];
    float* Xs = sm;                   // [128][XROW]
    float* Ws = sm + BM * XROW;       // [128][XROW]
    __shared__ int   s_am[D];
    __shared__ float s_dv[D];
    __shared__ float s_bs[D];

    int bid = blockIdx.x;
    int g, n, t, L, wboff;
    const float* x; const float* W; float* y;
    if (bid < NBLK0) {
        g = 0; n = bid >> 4; t = bid & 15; L = L0; wboff = D;
        x = x0; W = W0; y = yout;
    } else {
        int b2 = bid - NBLK0;
        g = 1; n = b2 >> 3; t = b2 & 7; L = L1; wboff = 2 * D;
        x = x1; W = W1; y = yout + (size_t)N_B * L0 * D;
    }
    int row0 = t * BM;
    int tid = threadIdx.x;

    // Stage x tile and W (first 128 cols), coalesced LDG + conflict-free STS
    const float* xb = x + ((size_t)n * L + row0) * D;
    #pragma unroll 4
    for (int i = tid; i < BM * D; i += 256) {
        int r = i >> 7, k = i & 127;
        Xs[r * XROW + k] = xb[(size_t)r * D + k];
    }
    #pragma unroll 4
    for (int i = tid; i < D * D; i += 256) {
        int o = i >> 7, k = i & 127;
        Ws[o * XROW + k] = W[(size_t)o * H + k];
    }
    if (tid < D) {
        s_am[tid] = g_amax[g][n][tid];
        s_dv[tid] = g_delta[g][n][tid];
        s_bs[tid] = g_base[g][n][tid];
    }
    __syncthreads();

    int rowg = tid & 15;   // rows: rowg + 16*i
    int colg = tid >> 4;   // cols: colg + 16*j

    unsigned long long acc[8][4];
    #pragma unroll
    for (int i = 0; i < 8; ++i)
        #pragma unroll
        for (int jp = 0; jp < 4; ++jp) acc[i][jp] = 0ULL;

    #pragma unroll 2
    for (int k = 0; k < D; ++k) {
        float xv[8], wv[8];
        #pragma unroll
        for (int i = 0; i < 8; ++i) xv[i] = Xs[(rowg + 16 * i) * XROW + k];
        #pragma unroll
        for (int j = 0; j < 8; ++j) wv[j] = Ws[(colg + 16 * j) * XROW + k];
        unsigned long long wp[4];
        #pragma unroll
        for (int jp = 0; jp < 4; ++jp) wp[jp] = pk2(wv[2 * jp], wv[2 * jp + 1]);
        #pragma unroll
        for (int i = 0; i < 8; ++i) {
            unsigned long long xbp = pk2(xv[i], xv[i]);
            #pragma unroll
            for (int jp = 0; jp < 4; ++jp)
                acc[i][jp] = fma2(xbp, wp[jp], acc[i][jp]);
        }
    }

    // Unpack + bias
    float av[8][8];
    #pragma unroll
    for (int i = 0; i < 8; ++i)
        #pragma unroll
        for (int jp = 0; jp < 4; ++jp)
            upk2(acc[i][jp], av[i][2 * jp], av[i][2 * jp + 1]);
    #pragma unroll
    for (int j = 0; j < 8; ++j) {
        float bz = s_bs[colg + 16 * j];
        #pragma unroll
        for (int i = 0; i < 8; ++i) av[i][j] += bz;
    }

    // Sparse LOO corrections (deterministic fixed ascending-d order)
    for (int d = 0; d < D; ++d) {
        int lr = s_am[d] - row0;
        if ((unsigned)lr < (unsigned)BM && (lr & 15) == rowg) {
            int i = lr >> 4;
            float dv = s_dv[d];
            const float* wr = W + wboff + d;
            #pragma unroll
            for (int j = 0; j < 8; ++j)
                av[i][j] += dv * wr[(size_t)(colg + 16 * j) * H];
        }
    }

    // Restage through smem -> coalesced float4 global stores
    __syncthreads();   // everyone done reading Xs/Ws
    float* Out = sm;   // [128][OROW]
    #pragma unroll
    for (int i = 0; i < 8; ++i) {
        int r = rowg + 16 * i;
        #pragma unroll
        for (int j = 0; j < 8; ++j)
            Out[r * OROW + colg + 16 * j] = av[i][j];
    }
    __syncthreads();
    float* yb = y + ((size_t)n * L + row0) * D;
    #pragma unroll
    for (int it = 0; it < 16; ++it) {
        int q = it * 256 + tid;
        int r = q >> 5, c4 = (q & 31) * 4;
        float4 v = *reinterpret_cast<const float4*>(&Out[r * OROW + c4]);
        *reinterpret_cast<float4*>(&yb[(size_t)r * D + c4]) = v;
    }
}

// ---------------------------------------------------------------------------
extern "C" void kernel_launch(void* const* d_in, const int* in_sizes, int n_in,
                              void* d_out, int out_size) {
    (void)in_sizes; (void)n_in; (void)out_size;
    const float* x0 = (const float*)d_in[0];
    const float* x1 = (const float*)d_in[1];
    const float* W0 = (const float*)d_in[2];
    const float* b0 = (const float*)d_in[3];
    const float* W1 = (const float*)d_in[4];
    const float* b1 = (const float*)d_in[5];
    float* y = (float*)d_out;

    const size_t smem = (size_t)(2 * BM * XROW) * sizeof(float); // 132096 B
    cudaFuncSetAttribute(gemm_kernel,
                         cudaFuncAttributeMaxDynamicSharedMemorySize, (int)smem);

    reduce_partial<<<dim3(CH0 + CH1, N_B), 128>>>(x0, x1);
    reduce_final<<<dim3(N_B, 2), 128>>>();
    base_kernel<<<dim3(N_B, 2), 512>>>(W0, b0, W1, b1);
    gemm_kernel<<<NBLK0 + NBLK1, 256, smem>>>(x0, x1, W0, W1, y);
}

// round 8
// speedup vs baseline: 1.5360x; 1.4311x over previous
#include <cuda_runtime.h>
#include <cuda_bf16.h>
#include <math.h>
#include <stdint.h>

#define N_B 16
#define D 128
#define L0 2048
#define L1 1024
#define H 384
#define CHUNK 64
#define CH0 (L0/CHUNK)   // 32
#define CH1 (L1/CHUNK)   // 16

#define BM 128
#define NBLK0 (N_B*(L0/BM))  // 256
#define NBLK1 (N_B*(L1/BM))  // 128
#define OROW 129
#define OUTROW 136

// Dynamic smem layout (bytes)
#define SO_AM   64                   // 128 ints
#define SO_DV   576                  // 128 floats
#define SO_BS   1088                 // 128 floats
#define SO_AF   4096                 // A fragments: 16 ksteps * 4KB = 65536
#define SO_BF   (SO_AF + 65536)      // B fragments: 16 ksteps * 4KB = 65536
#define SO_OBC  (SO_BF + 65536)      // bias+corr [128][OROW] f32 = 66048
#define SMEM_TC (SO_OBC + BM * OROW * 4)   // 201216 bytes

// Scratch (device globals; no allocation allowed)
__device__ float g_pm1[2][N_B][CH0][D];
__device__ float g_pm2[2][N_B][CH0][D];
__device__ int   g_pam[2][N_B][CH0][D];
__device__ float g_top1[2][N_B][D];
__device__ float g_delta[2][N_B][D];
__device__ int   g_amax[2][N_B][D];
__device__ float g_base[2][N_B][D];

// ---------------------------------------------------------------------------
// m16n8k16 bf16 MMA (stable ISA, works on plain sm_103 target)
// ---------------------------------------------------------------------------
__device__ __forceinline__ void mma_bf16(float* d, const uint32_t* a, const uint32_t* b) {
    asm volatile(
        "mma.sync.aligned.m16n8k16.row.col.f32.bf16.bf16.f32 "
        "{%0,%1,%2,%3}, {%4,%5,%6,%7}, {%8,%9}, {%0,%1,%2,%3};\n"
        : "+f"(d[0]), "+f"(d[1]), "+f"(d[2]), "+f"(d[3])
        : "r"(a[0]), "r"(a[1]), "r"(a[2]), "r"(a[3]), "r"(b[0]), "r"(b[1]));
}

// hi/lo bf16x2 split of a float2 (exact residual split)
__device__ __forceinline__ void split2(float2 v, uint32_t& hi, uint32_t& lo) {
    __nv_bfloat162 h = __float22bfloat162_rn(v);
    float2 hf = __bfloat1622float2(h);
    __nv_bfloat162 l = __float22bfloat162_rn(make_float2(v.x - hf.x, v.y - hf.y));
    hi = *(uint32_t*)&h;
    lo = *(uint32_t*)&l;
}

// ---------------------------------------------------------------------------
// Stage 1: per-chunk top2 + argmax (both groups in one launch)
// ---------------------------------------------------------------------------
__global__ void reduce_partial(const float* __restrict__ x0,
                               const float* __restrict__ x1) {
    int n = blockIdx.y, c = blockIdx.x, d = threadIdx.x;
    int g, cc, L;
    const float* x;
    if (c < CH0) { g = 0; cc = c;       L = L0; x = x0; }
    else         { g = 1; cc = c - CH0; L = L1; x = x1; }
    const float* p = x + ((size_t)n * L + (size_t)cc * CHUNK) * D + d;
    float m1 = -INFINITY, m2 = -INFINITY;
    int am = 0;
    for (int r0 = 0; r0 < CHUNK; r0 += 8) {
        float v[8];
        #pragma unroll
        for (int u = 0; u < 8; ++u) v[u] = p[(size_t)(r0 + u) * D];
        #pragma unroll
        for (int u = 0; u < 8; ++u) {
            if (v[u] > m1) { m2 = m1; m1 = v[u]; am = cc * CHUNK + r0 + u; }
            else if (v[u] > m2) { m2 = v[u]; }
        }
    }
    g_pm1[g][n][cc][d] = m1;
    g_pm2[g][n][cc][d] = m2;
    g_pam[g][n][cc][d] = am;
}

// ---------------------------------------------------------------------------
// Stage 2: merge partials -> top1 / (top2-top1) / argmax
// ---------------------------------------------------------------------------
__global__ void reduce_final() {
    int n = blockIdx.x, g = blockIdx.y, d = threadIdx.x;
    int CH = g ? CH1 : CH0;
    float m1 = -INFINITY, m2 = -INFINITY;
    int am = 0;
    for (int c = 0; c < CH; ++c) {
        float p1 = g_pm1[g][n][c][d];
        float p2 = g_pm2[g][n][c][d];
        int   pa = g_pam[g][n][c][d];
        if (p1 > m1) { m2 = fmaxf(m1, p2); m1 = p1; am = pa; }
        else         { m2 = fmaxf(m2, p1); }
    }
    g_top1[g][n][d]  = m1;
    g_delta[g][n][d] = m2 - m1;
    g_amax[g][n][d]  = am;
}

// ---------------------------------------------------------------------------
// Stage 3: per-(g,n,o) bias  base = b[o] + top1_x0·W[o,128:256] + top1_x1·W[o,256:384]
// ---------------------------------------------------------------------------
__global__ void base_kernel(const float* __restrict__ W0, const float* __restrict__ b0,
                            const float* __restrict__ W1, const float* __restrict__ b1) {
    int n = blockIdx.x, g = blockIdx.y;
    const float* W = g ? W1 : W0;
    const float* b = g ? b1 : b0;
    int tid = threadIdx.x;   // 512
    __shared__ float tv[2 * D];
    if (tid < D)          tv[tid] = g_top1[0][n][tid];
    else if (tid < 2 * D) tv[tid] = g_top1[1][n][tid - D];
    __syncthreads();
    int lane = tid & 31, w = tid >> 5;
    #pragma unroll
    for (int oo = 0; oo < 8; ++oo) {
        int o = w + 16 * oo;
        const float* wr = W + (size_t)o * H + D;
        float s = 0.0f;
        #pragma unroll
        for (int c = 0; c < 8; ++c) { int dd = lane + 32 * c; s += tv[dd] * wr[dd]; }
        #pragma unroll
        for (int off = 16; off; off >>= 1) s += __shfl_down_sync(0xffffffffu, s, off);
        if (lane == 0) g_base[g][n][o] = s + b[o];
    }
}

// ---------------------------------------------------------------------------
// Stage 4: HMMA GEMM, bf16 hi/lo 3-pass split, fragments pre-swizzled in smem.
//   y[n,l,o] = x·W[:, :128]^T + base + sparse LOO corrections
// Block 128x128, 8 warps in 4(M) x 2(N); warp tile 32x64.
// ---------------------------------------------------------------------------
__global__ void __launch_bounds__(256, 1)
gemm_mma(const float* __restrict__ x0, const float* __restrict__ x1,
         const float* __restrict__ W0, const float* __restrict__ W1,
         float* __restrict__ yout) {
    extern __shared__ char sm[];

    int bid = blockIdx.x;
    int g, n, t, L, wboff;
    const float* x; const float* W; float* y;
    if (bid < NBLK0) {
        g = 0; n = bid >> 4; t = bid & 15; L = L0; wboff = D;
        x = x0; W = W0; y = yout;
    } else {
        int b2 = bid - NBLK0;
        g = 1; n = b2 >> 3; t = b2 & 7; L = L1; wboff = 2 * D;
        x = x1; W = W1; y = yout + (size_t)N_B * L0 * D;
    }
    int row0 = t * BM;
    int tid = threadIdx.x, wid = tid >> 5, lane = tid & 31;

    int*      s_am = (int*)(sm + SO_AM);
    float*    s_dv = (float*)(sm + SO_DV);
    float*    s_bs = (float*)(sm + SO_BS);
    uint32_t* AF   = (uint32_t*)(sm + SO_AF);
    uint32_t* BF   = (uint32_t*)(sm + SO_BF);
    float*    Obc  = (float*)(sm + SO_OBC);

    if (tid < D) {
        s_am[tid] = g_amax[g][n][tid];
        s_dv[tid] = g_delta[g][n][tid];
        s_bs[tid] = g_base[g][n][tid];
    }

    // ---- Stage A (x tile) into fragment order, hi (ksteps 0-7) / lo (8-15)
    // A frag m16n8k16: reg = (khalf<<1)|rowhalf; lane = (r&7)*4 + (kinp&3)
    const float* xb = x + ((size_t)n * L + row0) * D;
    #pragma unroll
    for (int it = 0; it < 32; ++it) {
        int p = tid + 256 * it;            // pair index over 128 rows x 64 kpairs
        int r = p >> 6, kp = p & 63;
        float2 v = *(const float2*)(xb + (size_t)r * D + 2 * kp);
        uint32_t hi, lo; split2(v, hi, lo);
        int kstep = kp >> 3, kinp = kp & 7;
        int khalf = kinp >> 2, t4 = kinp & 3;
        int ln = ((r & 7) << 2) | t4;
        int mt = r >> 4, rhalf = (r >> 3) & 1;
        int reg = (khalf << 1) | rhalf;
        int idx = ((kstep << 3) + mt) * 128 + (ln << 2) + reg;
        AF[idx] = hi;
        AF[idx + 8 * 1024] = lo;
    }
    // ---- Stage B (W[:, :128]) into fragment order, hi / lo
    // B frag: reg = khalf; lane = (o&7)*4 + (kinp&3)
    #pragma unroll
    for (int it = 0; it < 32; ++it) {
        int p = tid + 256 * it;            // over 128 o-rows x 64 kpairs
        int o = p >> 6, kp = p & 63;
        float2 v = *(const float2*)(W + (size_t)o * H + 2 * kp);
        uint32_t hi, lo; split2(v, hi, lo);
        int kstep = kp >> 3, kinp = kp & 7;
        int khalf = kinp >> 2, t4 = kinp & 3;
        int ln = ((o & 7) << 2) | t4;
        int nt = o >> 3;
        int idx = ((kstep << 4) + nt) * 64 + (ln << 1) + khalf;
        BF[idx] = hi;
        BF[idx + 8 * 1024] = lo;
    }
    __syncthreads();

    // ---- Bias + sparse LOO corrections into Obc (before MMA; Obc is disjoint)
    for (int i = tid; i < BM * D; i += 256) {
        int r = i >> 7, c = i & 127;
        Obc[r * OROW + c] = s_bs[c];
    }
    __syncthreads();
    for (int d = 0; d < D; ++d) {
        int lr = s_am[d] - row0;
        if ((unsigned)lr < (unsigned)BM && (lr & 7) == wid) {   // warp-owned rows
            float dv = s_dv[d];
            const float* wr = W + wboff + d;
            #pragma unroll
            for (int c = lane; c < D; c += 32)
                Obc[lr * OROW + c] += dv * wr[(size_t)c * H];
        }
    }

    // ---- MMA mainloop: 24 ksteps (hi*hi x8, hi*lo x8, lo*hi x8)
    int warp_m = wid & 3, warp_n = wid >> 2;
    float acc[2][8][4];
    #pragma unroll
    for (int mt = 0; mt < 2; ++mt)
        #pragma unroll
        for (int nt = 0; nt < 8; ++nt)
            #pragma unroll
            for (int q = 0; q < 4; ++q) acc[mt][nt][q] = 0.0f;

    #pragma unroll
    for (int s = 0; s < 24; ++s) {
        int as = (s < 16) ? (s & 7) + ((s >> 3) == 1 ? 0 : 0) : (8 + s - 16);
        // A slot: s 0-7 -> hi[s], 8-15 -> hi[s-8], 16-23 -> lo[s-16]
        as = (s < 8) ? s : (s < 16 ? s - 8 : 8 + (s - 16));
        // B slot: s 0-7 -> hi[s], 8-15 -> lo[s-8], 16-23 -> hi[s-16]
        int bs = (s < 8) ? s : (s < 16 ? 8 + (s - 8) : s - 16);

        const uint32_t* ab = AF + ((as << 3) + (warp_m << 1)) * 128;
        const uint32_t* bb = BF + ((bs << 4) + (warp_n << 3)) * 64;

        uint32_t afr[2][4];
        #pragma unroll
        for (int mt = 0; mt < 2; ++mt) {
            uint4 v = ((const uint4*)(ab + mt * 128))[lane];
            afr[mt][0] = v.x; afr[mt][1] = v.y; afr[mt][2] = v.z; afr[mt][3] = v.w;
        }
        uint32_t bfr[8][2];
        #pragma unroll
        for (int nt = 0; nt < 8; ++nt) {
            uint2 w = ((const uint2*)(bb + nt * 64))[lane];
            bfr[nt][0] = w.x; bfr[nt][1] = w.y;
        }
        #pragma unroll
        for (int mt = 0; mt < 2; ++mt)
            #pragma unroll
            for (int nt = 0; nt < 8; ++nt)
                mma_bf16(acc[mt][nt], afr[mt], bfr[nt]);
    }

    // ---- Restage accumulators through smem (reuse AF/BF region), coalesced out
    __syncthreads();                     // all warps done reading AF/BF
    float* Out = (float*)(sm + SO_AF);   // [128][OUTROW]
    int gq = lane >> 2, t4q = lane & 3;
    #pragma unroll
    for (int mt = 0; mt < 2; ++mt) {
        int rbase = warp_m * 32 + mt * 16 + gq;
        #pragma unroll
        for (int nt = 0; nt < 8; ++nt) {
            int c = warp_n * 64 + nt * 8 + 2 * t4q;
            *(float2*)&Out[rbase * OUTROW + c]       = make_float2(acc[mt][nt][0], acc[mt][nt][1]);
            *(float2*)&Out[(rbase + 8) * OUTROW + c] = make_float2(acc[mt][nt][2], acc[mt][nt][3]);
        }
    }
    __syncthreads();

    float* yb = y + ((size_t)n * L + row0) * D;
    #pragma unroll
    for (int it = 0; it < 16; ++it) {
        int q = it * 256 + tid;
        int r = q >> 5, c4 = (q & 31) * 4;
        float4 v = *(const float4*)&Out[r * OUTROW + c4];
        v.x += Obc[r * OROW + c4];
        v.y += Obc[r * OROW + c4 + 1];
        v.z += Obc[r * OROW + c4 + 2];
        v.w += Obc[r * OROW + c4 + 3];
        *(float4*)&yb[(size_t)r * D + c4] = v;
    }
}

// ---------------------------------------------------------------------------
extern "C" void kernel_launch(void* const* d_in, const int* in_sizes, int n_in,
                              void* d_out, int out_size) {
    (void)in_sizes; (void)n_in; (void)out_size;
    const float* x0 = (const float*)d_in[0];
    const float* x1 = (const float*)d_in[1];
    const float* W0 = (const float*)d_in[2];
    const float* b0 = (const float*)d_in[3];
    const float* W1 = (const float*)d_in[4];
    const float* b1 = (const float*)d_in[5];
    float* y = (float*)d_out;

    cudaFuncSetAttribute(gemm_mma, cudaFuncAttributeMaxDynamicSharedMemorySize, SMEM_TC);

    reduce_partial<<<dim3(CH0 + CH1, N_B), 128>>>(x0, x1);
    reduce_final<<<dim3(N_B, 2), 128>>>();
    base_kernel<<<dim3(N_B, 2), 512>>>(W0, b0, W1, b1);
    gemm_mma<<<NBLK0 + NBLK1, 256, SMEM_TC>>>(x0, x1, W0, W1, y);
}